// round 8
// baseline (speedup 1.0000x reference)
#include <cuda_runtime.h>
#include <cstdint>

// ---------------- problem constants ----------------
#define HWDIM 96
#define PIX   9216          // 96*96
#define NG    1024          // groups per image (32*32)
#define SCALE 0.17677669529663687f   // 32^-0.5

// ---------------- scratch (static device globals; no allocation) ----------------
__device__ float g_qkv[113246208];   // [b][768][9216]
__device__ float g_tok[768];
__device__ float g_t[4194304];       // [b][256][1024]
__device__ float g_gf[37748736];     // [(b*8+h)*1024 + g][9][32]
__device__ float g_wq[4194304];      // [(b*8+h)*1024 + n][32]
__device__ float g_wkt[4194304];     // [(b*8+h)*32 + d][1024]
__device__ float g_dots[134217728];  // [(b*8+h)][1024][1024]  raw scaled logits
__device__ unsigned g_rmax[131072];  // per-row encoded max
__device__ float g_agg[37748736];    // [(b*8+h)*1024 + i][9][32]

__device__ __forceinline__ float allsum(float v){
  #pragma unroll
  for (int o = 16; o > 0; o >>= 1) v += __shfl_xor_sync(0xffffffffu, v, o);
  return v;
}
__device__ __forceinline__ unsigned fenc(float f){
  unsigned u = __float_as_uint(f);
  return (u & 0x80000000u) ? ~u : (u | 0x80000000u);
}
__device__ __forceinline__ float fdec(unsigned u){
  return (u & 0x80000000u) ? __uint_as_float(u ^ 0x80000000u) : __uint_as_float(~u);
}
__device__ __forceinline__ float fexp(float x){
  x = fmaxf(x, -80.f);
  float t = fmaf(x, 1.4426950408889634f, 12582912.f);
  int e = __float_as_int(t) << 23;
  float i = t - 12582912.f;
  float f = fmaf(x, 1.4426950408889634f, -i);
  float p =       1.3333558e-3f;
  p = fmaf(p, f, 9.6181291e-3f);
  p = fmaf(p, f, 5.5504109e-2f);
  p = fmaf(p, f, 2.4022651e-1f);
  p = fmaf(p, f, 6.9314718e-1f);
  p = fmaf(p, f, 1.0f);
  return __int_as_float(__float_as_int(p) + e);
}
__device__ __forceinline__ uint32_t f2tf32(float v){
  uint32_t t;
  asm("cvt.rna.tf32.f32 %0, %1;" : "=r"(t) : "f"(v));
  return t;
}
__device__ __forceinline__ void mma_tf32(float* d, const uint32_t* a, const uint32_t* b){
  asm volatile(
    "mma.sync.aligned.m16n8k8.row.col.f32.tf32.tf32.f32 "
    "{%0,%1,%2,%3}, {%4,%5,%6,%7}, {%8,%9}, {%0,%1,%2,%3};\n"
    : "+f"(d[0]), "+f"(d[1]), "+f"(d[2]), "+f"(d[3])
    : "r"(a[0]), "r"(a[1]), "r"(a[2]), "r"(a[3]), "r"(b[0]), "r"(b[1]));
}

// ---------------- K-1: zero rowmax ----------------
__global__ void k_zero(){
  ((uint4*)g_rmax)[blockIdx.x * 256 + threadIdx.x] = make_uint4(0,0,0,0);
}

// ---------------- K0: qkv of the shared group token ----------------
__global__ void k_tok(const float* __restrict__ w, const float* __restrict__ tok){
  int o = blockIdx.x * 256 + threadIdx.x;
  if (o < 768){
    const float* wr = w + o * 256;
    float s = 0.f;
    #pragma unroll 8
    for (int c = 0; c < 256; c++) s += wr[c] * tok[c];
    g_tok[o] = s;
  }
}

// ---------------- K1: qkv GEMM (tf32, double-buffered)  M=768, K=256, N=147456 ----------
__global__ __launch_bounds__(256) void k_qkv(const float* __restrict__ A,
                                             const float* __restrict__ X){
  __shared__ uint32_t As[2][16][132];
  __shared__ uint32_t Bs[2][16][132];
  int tid = threadIdx.x;
  int lane = tid & 31, warp = tid >> 5;
  int warpM = warp >> 1, warpN = warp & 1;
  int m0 = blockIdx.y * 128;
  int n0 = blockIdx.x * 128;
  int b = n0 / PIX;
  int pix0 = n0 - b * PIX;
  const float* Bp = X + (size_t)b * 256 * PIX + pix0;

  float acc[2][8][4];
  #pragma unroll
  for (int mt = 0; mt < 2; mt++)
    #pragma unroll
    for (int nt = 0; nt < 8; nt++)
      #pragma unroll
      for (int i = 0; i < 4; i++) acc[mt][nt][i] = 0.f;

  int ar = tid >> 1, ac = (tid & 1) * 8;
  int br = tid >> 4, bc = (tid & 15) * 8;
  const float* Arow = A + (m0 + ar) * 256 + ac;
  const float* Brow = Bp + (size_t)br * PIX + bc;

  // prologue: stage 0
  float4 a0 = *(const float4*)(Arow);
  float4 a1 = *(const float4*)(Arow + 4);
  float4 b0 = *(const float4*)(Brow);
  float4 b1 = *(const float4*)(Brow + 4);
  As[0][ac+0][ar]=f2tf32(a0.x); As[0][ac+1][ar]=f2tf32(a0.y);
  As[0][ac+2][ar]=f2tf32(a0.z); As[0][ac+3][ar]=f2tf32(a0.w);
  As[0][ac+4][ar]=f2tf32(a1.x); As[0][ac+5][ar]=f2tf32(a1.y);
  As[0][ac+6][ar]=f2tf32(a1.z); As[0][ac+7][ar]=f2tf32(a1.w);
  Bs[0][br][bc+0]=f2tf32(b0.x); Bs[0][br][bc+1]=f2tf32(b0.y);
  Bs[0][br][bc+2]=f2tf32(b0.z); Bs[0][br][bc+3]=f2tf32(b0.w);
  Bs[0][br][bc+4]=f2tf32(b1.x); Bs[0][br][bc+5]=f2tf32(b1.y);
  Bs[0][br][bc+6]=f2tf32(b1.z); Bs[0][br][bc+7]=f2tf32(b1.w);
  __syncthreads();

  for (int t = 0; t < 16; t++){
    int cur = t & 1;
    if (t < 15){
      a0 = *(const float4*)(Arow + (t+1) * 16);
      a1 = *(const float4*)(Arow + (t+1) * 16 + 4);
      b0 = *(const float4*)(Brow + (size_t)(t+1) * 16 * PIX);
      b1 = *(const float4*)(Brow + (size_t)(t+1) * 16 * PIX + 4);
    }
    #pragma unroll
    for (int kk = 0; kk < 16; kk += 8){
      uint32_t af[2][4], bf[8][2];
      int kr = kk + (lane & 3);
      #pragma unroll
      for (int mt = 0; mt < 2; mt++){
        int rb = warpM * 32 + mt * 16 + (lane >> 2);
        af[mt][0] = As[cur][kr    ][rb];
        af[mt][1] = As[cur][kr    ][rb + 8];
        af[mt][2] = As[cur][kr + 4][rb];
        af[mt][3] = As[cur][kr + 4][rb + 8];
      }
      #pragma unroll
      for (int nt = 0; nt < 8; nt++){
        int nb = warpN * 64 + nt * 8 + (lane >> 2);
        bf[nt][0] = Bs[cur][kr    ][nb];
        bf[nt][1] = Bs[cur][kr + 4][nb];
      }
      #pragma unroll
      for (int mt = 0; mt < 2; mt++)
        #pragma unroll
        for (int nt = 0; nt < 8; nt++)
          mma_tf32(acc[mt][nt], af[mt], bf[nt]);
    }
    if (t < 15){
      int nxt = 1 - cur;
      As[nxt][ac+0][ar]=f2tf32(a0.x); As[nxt][ac+1][ar]=f2tf32(a0.y);
      As[nxt][ac+2][ar]=f2tf32(a0.z); As[nxt][ac+3][ar]=f2tf32(a0.w);
      As[nxt][ac+4][ar]=f2tf32(a1.x); As[nxt][ac+5][ar]=f2tf32(a1.y);
      As[nxt][ac+6][ar]=f2tf32(a1.z); As[nxt][ac+7][ar]=f2tf32(a1.w);
      Bs[nxt][br][bc+0]=f2tf32(b0.x); Bs[nxt][br][bc+1]=f2tf32(b0.y);
      Bs[nxt][br][bc+2]=f2tf32(b0.z); Bs[nxt][br][bc+3]=f2tf32(b0.w);
      Bs[nxt][br][bc+4]=f2tf32(b1.x); Bs[nxt][br][bc+5]=f2tf32(b1.y);
      Bs[nxt][br][bc+6]=f2tf32(b1.z); Bs[nxt][br][bc+7]=f2tf32(b1.w);
    }
    __syncthreads();
  }
  float* outp = g_qkv + (size_t)b * 768 * PIX + pix0;
  #pragma unroll
  for (int mt = 0; mt < 2; mt++){
    #pragma unroll
    for (int ii = 0; ii < 2; ii++){
      int o = m0 + warpM * 32 + mt * 16 + (lane >> 2) + ii * 8;
      #pragma unroll
      for (int nt = 0; nt < 8; nt++){
        int col = warpN * 64 + nt * 8 + (lane & 3) * 2;
        float2 v = make_float2(acc[mt][nt][ii*2], acc[mt][nt][ii*2+1]);
        *(float2*)&outp[(size_t)o * PIX + col] = v;
      }
    }
  }
}

// ---------------- K2: per-group 10-token attention + LN + GELU (shuffle-free dots) ------
__global__ __launch_bounds__(256) void k_attn1(const float* __restrict__ gamma,
                                               const float* __restrict__ beta){
  __shared__ __align__(16) float qt[8][10][36];
  __shared__ __align__(16) float kt[8][10][36];
  __shared__ __align__(16) float vt[8][10][36];
  __shared__ float sd[8][10][11];
  int gidx = blockIdx.x;
  int b = gidx >> 10, g = gidx & 1023;
  int gy = g >> 5, gx = g & 31;
  int tid = threadIdx.x;

  const float* src = g_qkv + (size_t)b * 768 * PIX + (gy * 3) * HWDIM + gx * 3;
  // token row (win slot 0)
  for (int i = tid; i < 768; i += 256){
    int sel = i >> 8, o = i & 255, h = o >> 5, d = o & 31;
    float (*dst)[10][36] = (sel == 0) ? qt : (sel == 1) ? kt : vt;
    dst[h][0][d] = g_tok[i];
  }
  // 9 pixel tokens (win slots 1..9)
  for (int i = tid; i < 6912; i += 256){
    int o3 = i / 9, win = i - o3 * 9;
    int sel = o3 >> 8, o = o3 & 255, h = o >> 5, d = o & 31;
    float v = src[(size_t)o3 * PIX + (win / 3) * HWDIM + (win % 3)];
    float (*dst)[10][36] = (sel == 0) ? qt : (sel == 1) ? kt : vt;
    dst[h][win + 1][d] = v;
  }
  __syncthreads();

  // dots + softmax: 80 threads, each owns (head, row i); no shuffles
  if (tid < 80){
    int h = tid / 10, i = tid - (tid / 10) * 10;
    float4 q0 = *(const float4*)&qt[h][i][0];
    float4 q1 = *(const float4*)&qt[h][i][4];
    float4 q2 = *(const float4*)&qt[h][i][8];
    float4 q3 = *(const float4*)&qt[h][i][12];
    float4 q4 = *(const float4*)&qt[h][i][16];
    float4 q5 = *(const float4*)&qt[h][i][20];
    float4 q6 = *(const float4*)&qt[h][i][24];
    float4 q7 = *(const float4*)&qt[h][i][28];
    float row[10];
    float m = -1e30f;
    #pragma unroll
    for (int j = 0; j < 10; j++){
      const float4* kv = (const float4*)&kt[h][j][0];
      float4 k0 = kv[0], k1 = kv[1], k2 = kv[2], k3 = kv[3];
      float4 k4 = kv[4], k5 = kv[5], k6 = kv[6], k7 = kv[7];
      float s = q0.x*k0.x + q0.y*k0.y + q0.z*k0.z + q0.w*k0.w;
      s = fmaf(q1.x,k1.x, fmaf(q1.y,k1.y, fmaf(q1.z,k1.z, fmaf(q1.w,k1.w, s))));
      s = fmaf(q2.x,k2.x, fmaf(q2.y,k2.y, fmaf(q2.z,k2.z, fmaf(q2.w,k2.w, s))));
      s = fmaf(q3.x,k3.x, fmaf(q3.y,k3.y, fmaf(q3.z,k3.z, fmaf(q3.w,k3.w, s))));
      s = fmaf(q4.x,k4.x, fmaf(q4.y,k4.y, fmaf(q4.z,k4.z, fmaf(q4.w,k4.w, s))));
      s = fmaf(q5.x,k5.x, fmaf(q5.y,k5.y, fmaf(q5.z,k5.z, fmaf(q5.w,k5.w, s))));
      s = fmaf(q6.x,k6.x, fmaf(q6.y,k6.y, fmaf(q6.z,k6.z, fmaf(q6.w,k6.w, s))));
      s = fmaf(q7.x,k7.x, fmaf(q7.y,k7.y, fmaf(q7.z,k7.z, fmaf(q7.w,k7.w, s))));
      row[j] = s * SCALE;
      m = fmaxf(m, row[j]);
    }
    float ssum = 0.f;
    #pragma unroll
    for (int j = 0; j < 10; j++){ row[j] = fexp(row[j] - m); ssum += row[j]; }
    float inv = 1.f / ssum;
    #pragma unroll
    for (int j = 0; j < 10; j++) sd[h][i][j] = row[j] * inv;
  }
  __syncthreads();

  // output: 256 threads, h = warp, lane = d
  int hh = tid >> 5, lane = tid & 31;
  float vr[10];
  #pragma unroll
  for (int j = 0; j < 10; j++) vr[j] = vt[hh][j][lane];

  float x0 = 0.f;
  #pragma unroll
  for (int j = 0; j < 10; j++) x0 = fmaf(sd[hh][0][j], vr[j], x0);
  float mu = allsum(x0) * 0.03125f;
  float dv = x0 - mu;
  float var = allsum(dv * dv) * 0.03125f;
  float xn = dv * rsqrtf(var + 1e-5f) * gamma[lane] + beta[lane];
  float ge = 0.5f * xn * (1.f + erff(xn * 0.70710678118654752f));
  int oq = hh * 32 + lane;
  g_t[b * 262144 + oq * 1024 + g] = ge;

  size_t gfb = ((size_t)(b * 8 + hh) * NG + g) * 288 + lane;
  #pragma unroll
  for (int i = 1; i < 10; i++){
    float o = 0.f;
    #pragma unroll
    for (int j = 0; j < 10; j++) o = fmaf(sd[hh][i][j], vr[j], o);
    g_gf[gfb + (i - 1) * 32] = o;
  }
}

// ---------------- K3: qk GEMM (tf32) per-batch M=512, K=256, N=1024 ----------------
__global__ __launch_bounds__(256) void k_qk(const float* __restrict__ A,
                                            const float* __restrict__ bias){
  __shared__ uint32_t As[16][132];
  __shared__ uint32_t Bs[16][132];
  int tid = threadIdx.x;
  int lane = tid & 31, warp = tid >> 5;
  int warpM = warp >> 1, warpN = warp & 1;
  int n0 = blockIdx.x * 128, m0 = blockIdx.y * 128, b = blockIdx.z;
  const float* Bp = g_t + b * 262144;

  float acc[2][8][4];
  #pragma unroll
  for (int mt = 0; mt < 2; mt++)
    #pragma unroll
    for (int nt = 0; nt < 8; nt++)
      #pragma unroll
      for (int i = 0; i < 4; i++) acc[mt][nt][i] = 0.f;

  int ar = tid >> 1, ac = (tid & 1) * 8;
  int br = tid >> 4, bc = (tid & 15) * 8;

  for (int k0 = 0; k0 < 256; k0 += 16){
    float4 a0 = *(const float4*)(A + (m0 + ar) * 256 + k0 + ac);
    float4 a1 = *(const float4*)(A + (m0 + ar) * 256 + k0 + ac + 4);
    As[ac+0][ar]=f2tf32(a0.x); As[ac+1][ar]=f2tf32(a0.y);
    As[ac+2][ar]=f2tf32(a0.z); As[ac+3][ar]=f2tf32(a0.w);
    As[ac+4][ar]=f2tf32(a1.x); As[ac+5][ar]=f2tf32(a1.y);
    As[ac+6][ar]=f2tf32(a1.z); As[ac+7][ar]=f2tf32(a1.w);
    float4 b0 = *(const float4*)(Bp + (k0 + br) * 1024 + n0 + bc);
    float4 b1 = *(const float4*)(Bp + (k0 + br) * 1024 + n0 + bc + 4);
    Bs[br][bc+0]=f2tf32(b0.x); Bs[br][bc+1]=f2tf32(b0.y);
    Bs[br][bc+2]=f2tf32(b0.z); Bs[br][bc+3]=f2tf32(b0.w);
    Bs[br][bc+4]=f2tf32(b1.x); Bs[br][bc+5]=f2tf32(b1.y);
    Bs[br][bc+6]=f2tf32(b1.z); Bs[br][bc+7]=f2tf32(b1.w);
    __syncthreads();
    #pragma unroll
    for (int kk = 0; kk < 16; kk += 8){
      uint32_t af[2][4], bf[8][2];
      int kr = kk + (lane & 3);
      #pragma unroll
      for (int mt = 0; mt < 2; mt++){
        int rb = warpM * 32 + mt * 16 + (lane >> 2);
        af[mt][0] = As[kr    ][rb];
        af[mt][1] = As[kr    ][rb + 8];
        af[mt][2] = As[kr + 4][rb];
        af[mt][3] = As[kr + 4][rb + 8];
      }
      #pragma unroll
      for (int nt = 0; nt < 8; nt++){
        int nb = warpN * 64 + nt * 8 + (lane >> 2);
        bf[nt][0] = Bs[kr    ][nb];
        bf[nt][1] = Bs[kr + 4][nb];
      }
      #pragma unroll
      for (int mt = 0; mt < 2; mt++)
        #pragma unroll
        for (int nt = 0; nt < 8; nt++)
          mma_tf32(acc[mt][nt], af[mt], bf[nt]);
    }
    __syncthreads();
  }
  #pragma unroll
  for (int mt = 0; mt < 2; mt++){
    #pragma unroll
    for (int ii = 0; ii < 2; ii++){
      int o = m0 + warpM * 32 + mt * 16 + (lane >> 2) + ii * 8;
      float bi = bias[o];
      int h = o >> 6, dd = o & 63;
      #pragma unroll
      for (int nt = 0; nt < 8; nt++){
        #pragma unroll
        for (int jj = 0; jj < 2; jj++){
          int n = n0 + warpN * 64 + nt * 8 + (lane & 3) * 2 + jj;
          float v = acc[mt][nt][ii * 2 + jj] + bi;
          if (dd < 32) g_wq[((b * 8 + h) * 1024 + n) * 32 + dd] = v;
          else         g_wkt[((b * 8 + h) * 32 + (dd - 32)) * 1024 + n] = v;
        }
      }
    }
  }
}

// ---------------- K4a: window dots (tf32) + rowmax reduce ----------------
__global__ __launch_bounds__(256) void k_dots(){
  __shared__ uint32_t As[32][132];
  __shared__ uint32_t Bs[32][132];
  int tid = threadIdx.x;
  int lane = tid & 31, warp = tid >> 5;
  int warpM = warp >> 1, warpN = warp & 1;
  int bh = blockIdx.z;
  int m0 = blockIdx.y * 128, n0 = blockIdx.x * 128;
  const float* Ap = g_wq + bh * 32768;
  const float* Bp = g_wkt + bh * 32768;

  int ar = tid >> 1, ac = (tid & 1) * 16;
  #pragma unroll
  for (int i = 0; i < 16; i += 4){
    float4 v = *(const float4*)(Ap + (m0 + ar) * 32 + ac + i);
    As[ac+i+0][ar]=f2tf32(v.x); As[ac+i+1][ar]=f2tf32(v.y);
    As[ac+i+2][ar]=f2tf32(v.z); As[ac+i+3][ar]=f2tf32(v.w);
  }
  int br = tid >> 3, bc = (tid & 7) * 16;
  #pragma unroll
  for (int i = 0; i < 16; i += 4){
    float4 v = *(const float4*)(Bp + br * 1024 + n0 + bc + i);
    Bs[br][bc+i+0]=f2tf32(v.x); Bs[br][bc+i+1]=f2tf32(v.y);
    Bs[br][bc+i+2]=f2tf32(v.z); Bs[br][bc+i+3]=f2tf32(v.w);
  }
  __syncthreads();

  float acc[2][8][4];
  #pragma unroll
  for (int mt = 0; mt < 2; mt++)
    #pragma unroll
    for (int nt = 0; nt < 8; nt++)
      #pragma unroll
      for (int i = 0; i < 4; i++) acc[mt][nt][i] = 0.f;

  #pragma unroll
  for (int kk = 0; kk < 32; kk += 8){
    uint32_t af[2][4], bf[8][2];
    int kr = kk + (lane & 3);
    #pragma unroll
    for (int mt = 0; mt < 2; mt++){
      int rb = warpM * 32 + mt * 16 + (lane >> 2);
      af[mt][0] = As[kr    ][rb];
      af[mt][1] = As[kr    ][rb + 8];
      af[mt][2] = As[kr + 4][rb];
      af[mt][3] = As[kr + 4][rb + 8];
    }
    #pragma unroll
    for (int nt = 0; nt < 8; nt++){
      int nb = warpN * 64 + nt * 8 + (lane >> 2);
      bf[nt][0] = Bs[kr    ][nb];
      bf[nt][1] = Bs[kr + 4][nb];
    }
    #pragma unroll
    for (int mt = 0; mt < 2; mt++)
      #pragma unroll
      for (int nt = 0; nt < 8; nt++)
        mma_tf32(acc[mt][nt], af[mt], bf[nt]);
  }
  float* out = g_dots + (size_t)bh * 1048576;
  unsigned* rmx = g_rmax + bh * 1024;
  #pragma unroll
  for (int mt = 0; mt < 2; mt++){
    #pragma unroll
    for (int ii = 0; ii < 2; ii++){
      int row = m0 + warpM * 32 + mt * 16 + (lane >> 2) + ii * 8;
      float rmax = -1e30f;
      #pragma unroll
      for (int nt = 0; nt < 8; nt++){
        int col = n0 + warpN * 64 + nt * 8 + (lane & 3) * 2;
        float2 v = make_float2(acc[mt][nt][ii*2] * SCALE, acc[mt][nt][ii*2+1] * SCALE);
        rmax = fmaxf(rmax, fmaxf(v.x, v.y));
        *(float2*)&out[(size_t)row * 1024 + col] = v;
      }
      rmax = fmaxf(rmax, __shfl_xor_sync(0xffffffffu, rmax, 1));
      rmax = fmaxf(rmax, __shfl_xor_sync(0xffffffffu, rmax, 2));
      if ((lane & 3) == 0) atomicMax(&rmx[row], fenc(rmax));
    }
  }
}

// ---------------- K4c: agg GEMM (tf32, double-buffered, fused softmax) ------------------
__global__ __launch_bounds__(256) void k_agg(){
  __shared__ uint32_t As[2][16][132];
  __shared__ uint32_t Bs[2][16][100];
  __shared__ float srow[128];
  int tid = threadIdx.x;
  int lane = tid & 31, warp = tid >> 5;
  int warpM = warp >> 1, warpN = warp & 1;
  int bh = blockIdx.z;
  int m0 = blockIdx.y * 128, n0 = blockIdx.x * 96;
  const float* Ap = g_dots + (size_t)bh * 1048576;
  const float* Bp = g_gf + (size_t)bh * 294912 + n0;

  if (tid < 128) srow[tid] = 0.f;

  float acc[2][6][4];
  #pragma unroll
  for (int mt = 0; mt < 2; mt++)
    #pragma unroll
    for (int nt = 0; nt < 6; nt++)
      #pragma unroll
      for (int i = 0; i < 4; i++) acc[mt][nt][i] = 0.f;

  int ar = tid >> 1, ac = (tid & 1) * 8;
  float rmx = fdec(g_rmax[bh * 1024 + m0 + ar]);
  float rsum = 0.f;
  const float* Arow = Ap + (size_t)(m0 + ar) * 1024 + ac;

  // B gather coords (6 elements per thread)
  int brr[6], bcc[6];
  #pragma unroll
  for (int l = 0; l < 6; l++){
    int li = tid + l * 256;
    brr[l] = li / 96; bcc[l] = li - brr[l] * 96;
  }

  // prologue: stage 0
  float ae[8]; float bv[6];
  {
    float4 a0 = *(const float4*)(Arow);
    float4 a1 = *(const float4*)(Arow + 4);
    ae[0]=fexp(a0.x-rmx); ae[1]=fexp(a0.y-rmx); ae[2]=fexp(a0.z-rmx); ae[3]=fexp(a0.w-rmx);
    ae[4]=fexp(a1.x-rmx); ae[5]=fexp(a1.y-rmx); ae[6]=fexp(a1.z-rmx); ae[7]=fexp(a1.w-rmx);
    #pragma unroll
    for (int i = 0; i < 8; i++){ rsum += ae[i]; As[0][ac+i][ar] = f2tf32(ae[i]); }
    #pragma unroll
    for (int l = 0; l < 6; l++)
      Bs[0][brr[l]][bcc[l]] = f2tf32(Bp[(size_t)brr[l] * 288 + bcc[l]]);
  }
  __syncthreads();

  for (int t = 0; t < 64; t++){
    int cur = t & 1;
    float4 a0, a1;
    if (t < 63){
      a0 = *(const float4*)(Arow + (t+1) * 16);
      a1 = *(const float4*)(Arow + (t+1) * 16 + 4);
      #pragma unroll
      for (int l = 0; l < 6; l++)
        bv[l] = Bp[(size_t)((t+1) * 16 + brr[l]) * 288 + bcc[l]];
    }
    #pragma unroll
    for (int kk = 0; kk < 16; kk += 8){
      uint32_t af[2][4], bf[6][2];
      int kr = kk + (lane & 3);
      #pragma unroll
      for (int mt = 0; mt < 2; mt++){
        int rb = warpM * 32 + mt * 16 + (lane >> 2);
        af[mt][0] = As[cur][kr    ][rb];
        af[mt][1] = As[cur][kr    ][rb + 8];
        af[mt][2] = As[cur][kr + 4][rb];
        af[mt][3] = As[cur][kr + 4][rb + 8];
      }
      #pragma unroll
      for (int nt = 0; nt < 6; nt++){
        int nb = warpN * 48 + nt * 8 + (lane >> 2);
        bf[nt][0] = Bs[cur][kr    ][nb];
        bf[nt][1] = Bs[cur][kr + 4][nb];
      }
      #pragma unroll
      for (int mt = 0; mt < 2; mt++)
        #pragma unroll
        for (int nt = 0; nt < 6; nt++)
          mma_tf32(acc[mt][nt], af[mt], bf[nt]);
    }
    if (t < 63){
      int nxt = 1 - cur;
      ae[0]=fexp(a0.x-rmx); ae[1]=fexp(a0.y-rmx); ae[2]=fexp(a0.z-rmx); ae[3]=fexp(a0.w-rmx);
      ae[4]=fexp(a1.x-rmx); ae[5]=fexp(a1.y-rmx); ae[6]=fexp(a1.z-rmx); ae[7]=fexp(a1.w-rmx);
      #pragma unroll
      for (int i = 0; i < 8; i++){ rsum += ae[i]; As[nxt][ac+i][ar] = f2tf32(ae[i]); }
      #pragma unroll
      for (int l = 0; l < 6; l++) Bs[nxt][brr[l]][bcc[l]] = f2tf32(bv[l]);
    }
    __syncthreads();
  }
  atomicAdd(&srow[ar], rsum);
  __syncthreads();

  float* out = g_agg + (size_t)bh * 294912;
  #pragma unroll
  for (int mt = 0; mt < 2; mt++){
    #pragma unroll
    for (int ii = 0; ii < 2; ii++){
      int rl = warpM * 32 + mt * 16 + (lane >> 2) + ii * 8;
      float inv = 1.f / srow[rl];
      int row = m0 + rl;
      #pragma unroll
      for (int nt = 0; nt < 6; nt++){
        int col = n0 + warpN * 48 + nt * 8 + (lane & 3) * 2;
        out[(size_t)row * 288 + col    ] = acc[mt][nt][ii * 2    ] * inv;
        out[(size_t)row * 288 + col + 1] = acc[mt][nt][ii * 2 + 1] * inv;
      }
    }
  }
}

// ---------------- K5: output projection (tf32, double-buffered) -------------------------
__global__ __launch_bounds__(256) void k_out(const float* __restrict__ W,
                                             const float* __restrict__ bias,
                                             float* __restrict__ out){
  __shared__ uint32_t As[2][16][132];
  __shared__ uint32_t Bs[2][16][132];
  int tid = threadIdx.x;
  int lane = tid & 31, warp = tid >> 5;
  int warpM = warp >> 1, warpN = warp & 1;
  int n0 = blockIdx.x * 128, m0 = blockIdx.y * 128;
  int b = n0 / PIX;
  int pix0 = n0 - b * PIX;

  int nb = tid & 127;
  int kh = tid >> 7;
  int pix = pix0 + nb;
  int y = pix / HWDIM, xc = pix - y * HWDIM;
  int g = (y / 3) * 32 + xc / 3;
  int win = (y % 3) * 3 + (xc % 3);
  size_t colbase = (size_t)b * 2359296 + (size_t)g * 288 + win * 32 + kh * 8;

  int ar = tid >> 1, ac = (tid & 1) * 8;
  const float* Arow = W + (m0 + ar) * 256 + ac;
  int kb = kh * 8;

  float acc[2][8][4];
  #pragma unroll
  for (int mt = 0; mt < 2; mt++)
    #pragma unroll
    for (int nt = 0; nt < 8; nt++)
      #pragma unroll
      for (int i = 0; i < 4; i++) acc[mt][nt][i] = 0.f;

  // prologue (t=0: h=0, dbase=kh*8)
  {
    float4 a0 = *(const float4*)(Arow);
    float4 a1 = *(const float4*)(Arow + 4);
    As[0][ac+0][ar]=f2tf32(a0.x); As[0][ac+1][ar]=f2tf32(a0.y);
    As[0][ac+2][ar]=f2tf32(a0.z); As[0][ac+3][ar]=f2tf32(a0.w);
    As[0][ac+4][ar]=f2tf32(a1.x); As[0][ac+5][ar]=f2tf32(a1.y);
    As[0][ac+6][ar]=f2tf32(a1.z); As[0][ac+7][ar]=f2tf32(a1.w);
    const float* bsrc = g_agg + colbase;
    float4 v0 = *(const float4*)(bsrc);
    float4 v1 = *(const float4*)(bsrc + 4);
    Bs[0][kb+0][nb]=f2tf32(v0.x); Bs[0][kb+1][nb]=f2tf32(v0.y);
    Bs[0][kb+2][nb]=f2tf32(v0.z); Bs[0][kb+3][nb]=f2tf32(v0.w);
    Bs[0][kb+4][nb]=f2tf32(v1.x); Bs[0][kb+5][nb]=f2tf32(v1.y);
    Bs[0][kb+6][nb]=f2tf32(v1.z); Bs[0][kb+7][nb]=f2tf32(v1.w);
  }
  __syncthreads();

  for (int t = 0; t < 16; t++){
    int cur = t & 1;
    float4 a0, a1, v0, v1;
    if (t < 15){
      a0 = *(const float4*)(Arow + (t+1) * 16);
      a1 = *(const float4*)(Arow + (t+1) * 16 + 4);
      int tn = t + 1;
      const float* bsrc = g_agg + colbase + (size_t)(tn >> 1) * 294912 + (tn & 1) * 16;
      v0 = *(const float4*)(bsrc);
      v1 = *(const float4*)(bsrc + 4);
    }
    #pragma unroll
    for (int kk = 0; kk < 16; kk += 8){
      uint32_t af[2][4], bf[8][2];
      int kr = kk + (lane & 3);
      #pragma unroll
      for (int mt = 0; mt < 2; mt++){
        int rb = warpM * 32 + mt * 16 + (lane >> 2);
        af[mt][0] = As[cur][kr    ][rb];
        af[mt][1] = As[cur][kr    ][rb + 8];
        af[mt][2] = As[cur][kr + 4][rb];
        af[mt][3] = As[cur][kr + 4][rb + 8];
      }
      #pragma unroll
      for (int nt = 0; nt < 8; nt++){
        int nbc = warpN * 64 + nt * 8 + (lane >> 2);
        bf[nt][0] = Bs[cur][kr    ][nbc];
        bf[nt][1] = Bs[cur][kr + 4][nbc];
      }
      #pragma unroll
      for (int mt = 0; mt < 2; mt++)
        #pragma unroll
        for (int nt = 0; nt < 8; nt++)
          mma_tf32(acc[mt][nt], af[mt], bf[nt]);
    }
    if (t < 15){
      int nxt = 1 - cur;
      As[nxt][ac+0][ar]=f2tf32(a0.x); As[nxt][ac+1][ar]=f2tf32(a0.y);
      As[nxt][ac+2][ar]=f2tf32(a0.z); As[nxt][ac+3][ar]=f2tf32(a0.w);
      As[nxt][ac+4][ar]=f2tf32(a1.x); As[nxt][ac+5][ar]=f2tf32(a1.y);
      As[nxt][ac+6][ar]=f2tf32(a1.z); As[nxt][ac+7][ar]=f2tf32(a1.w);
      Bs[nxt][kb+0][nb]=f2tf32(v0.x); Bs[nxt][kb+1][nb]=f2tf32(v0.y);
      Bs[nxt][kb+2][nb]=f2tf32(v0.z); Bs[nxt][kb+3][nb]=f2tf32(v0.w);
      Bs[nxt][kb+4][nb]=f2tf32(v1.x); Bs[nxt][kb+5][nb]=f2tf32(v1.y);
      Bs[nxt][kb+6][nb]=f2tf32(v1.z); Bs[nxt][kb+7][nb]=f2tf32(v1.w);
    }
    __syncthreads();
  }
  float* op = out + ((size_t)b * 256) * PIX + pix0;
  #pragma unroll
  for (int mt = 0; mt < 2; mt++){
    #pragma unroll
    for (int ii = 0; ii < 2; ii++){
      int o = m0 + warpM * 32 + mt * 16 + (lane >> 2) + ii * 8;
      float bi = bias[o];
      #pragma unroll
      for (int nt = 0; nt < 8; nt++){
        int col = warpN * 64 + nt * 8 + (lane & 3) * 2;
        float2 v = make_float2(acc[mt][nt][ii*2] + bi, acc[mt][nt][ii*2+1] + bi);
        *(float2*)&op[(size_t)o * PIX + col] = v;
      }
    }
  }
}

// ---------------- launch ----------------
extern "C" void kernel_launch(void* const* d_in, const int* in_sizes, int n_in,
                              void* d_out, int out_size){
  const float* x      = (const float*)d_in[0];
  const float* w_qkv  = (const float*)d_in[1];
  const float* gtok   = (const float*)d_in[2];
  const float* gamma  = (const float*)d_in[3];
  const float* beta   = (const float*)d_in[4];
  const float* w_qk   = (const float*)d_in[5];
  const float* b_qk   = (const float*)d_in[6];
  const float* w_out  = (const float*)d_in[7];
  const float* b_out  = (const float*)d_in[8];
  float* out = (float*)d_out;

  k_zero <<<128, 256>>>();
  k_tok  <<<3, 256>>>(w_qkv, gtok);
  k_qkv  <<<dim3(1152, 6), 256>>>(w_qkv, x);
  k_attn1<<<16384, 256>>>(gamma, beta);
  k_qk   <<<dim3(8, 4, 16), 256>>>(w_qk, b_qk);
  k_dots <<<dim3(8, 8, 128), 256>>>();
  k_agg  <<<dim3(3, 8, 128), 256>>>();
  k_out  <<<dim3(1152, 2), 256>>>(w_out, b_out, out);
}

// round 13
// speedup vs baseline: 1.7743x; 1.7743x over previous
#include <cuda_runtime.h>
#include <cstdint>

// ---------------- problem constants ----------------
#define HWDIM 96
#define PIX   9216
#define NG    1024
#define SCALE 0.17677669529663687f

// ---------------- scratch ----------------
__device__ float g_qkv[113246208];   // [b][768][9216]
__device__ float g_tok[768];
__device__ float g_t[4194304];       // [b][256][1024]
__device__ float g_gf[37748736];     // [(b*8+h)*1024+g][9][32]  (tf32-rounded)
__device__ float g_wq[4194304];
__device__ float g_wkt[4194304];
__device__ float g_dots[134217728];  // logits -> exp'd tf32-rounded after k_exp
__device__ unsigned g_rmax[131072];
__device__ float g_rsum[131072];
__device__ float g_agg[37748736];    // tf32-rounded
__device__ float g_x[37748736];      // tf32-rounded x
__device__ float g_wqkv[196608];     // tf32-rounded w_qkv
__device__ float g_wo[65536];        // tf32-rounded w_out

__device__ __forceinline__ float allsum(float v){
  #pragma unroll
  for (int o = 16; o > 0; o >>= 1) v += __shfl_xor_sync(0xffffffffu, v, o);
  return v;
}
__device__ __forceinline__ unsigned fenc(float f){
  unsigned u = __float_as_uint(f);
  return (u & 0x80000000u) ? ~u : (u | 0x80000000u);
}
__device__ __forceinline__ float fdec(unsigned u){
  return (u & 0x80000000u) ? __uint_as_float(u ^ 0x80000000u) : __uint_as_float(~u);
}
__device__ __forceinline__ float fexp(float x){
  x = fmaxf(x, -80.f);
  float t = fmaf(x, 1.4426950408889634f, 12582912.f);
  int e = __float_as_int(t) << 23;
  float i = t - 12582912.f;
  float f = fmaf(x, 1.4426950408889634f, -i);
  float p =       1.3333558e-3f;
  p = fmaf(p, f, 9.6181291e-3f);
  p = fmaf(p, f, 5.5504109e-2f);
  p = fmaf(p, f, 2.4022651e-1f);
  p = fmaf(p, f, 6.9314718e-1f);
  p = fmaf(p, f, 1.0f);
  return __int_as_float(__float_as_int(p) + e);
}
__device__ __forceinline__ uint32_t f2tf32(float v){
  uint32_t t;
  asm("cvt.rna.tf32.f32 %0, %1;" : "=r"(t) : "f"(v));
  return t;
}
__device__ __forceinline__ float roundtf(float v){ return __uint_as_float(f2tf32(v)); }
__device__ __forceinline__ void mma_tf32(float* d, const uint32_t* a, const uint32_t* b){
  asm volatile(
    "mma.sync.aligned.m16n8k8.row.col.f32.tf32.tf32.f32 "
    "{%0,%1,%2,%3}, {%4,%5,%6,%7}, {%8,%9}, {%0,%1,%2,%3};\n"
    : "+f"(d[0]), "+f"(d[1]), "+f"(d[2]), "+f"(d[3])
    : "r"(a[0]), "r"(a[1]), "r"(a[2]), "r"(a[3]), "r"(b[0]), "r"(b[1]));
}
__device__ __forceinline__ void cp16(void* smem, const void* gmem){
  uint32_t s = (uint32_t)__cvta_generic_to_shared(smem);
  asm volatile("cp.async.cg.shared.global [%0], [%1], 16;\n" :: "r"(s), "l"(gmem));
}
#define CP_COMMIT() asm volatile("cp.async.commit_group;\n")
#define CP_WAIT1()  asm volatile("cp.async.wait_group 1;\n")

// ---------------- utility kernels ----------------
__global__ void k_zero(){
  ((uint4*)g_rmax)[blockIdx.x * 256 + threadIdx.x] = make_uint4(0,0,0,0);
}
__global__ void k_round(float* __restrict__ dst, const float* __restrict__ src, int n4){
  int i = blockIdx.x * 256 + threadIdx.x;
  if (i < n4){
    float4 v = ((const float4*)src)[i];
    v.x = roundtf(v.x); v.y = roundtf(v.y); v.z = roundtf(v.z); v.w = roundtf(v.w);
    ((float4*)dst)[i] = v;
  }
}
__global__ void k_tok(const float* __restrict__ w, const float* __restrict__ tok){
  int o = blockIdx.x * 256 + threadIdx.x;
  if (o < 768){
    const float* wr = w + o * 256;
    float s = 0.f;
    #pragma unroll 8
    for (int c = 0; c < 256; c++) s += wr[c] * tok[c];
    g_tok[o] = s;
  }
}

// ---------------- K1: qkv GEMM (tf32, cp.async 2-stage)  M=768,K=256,N=147456 -----------
__global__ __launch_bounds__(256) void k_qkv(){
  __shared__ __align__(16) uint32_t Asm[2][128][20];   // [m][k] raw (pre-rounded)
  __shared__ __align__(16) uint32_t Bsm[2][16][132];   // [k][n]
  int tid = threadIdx.x;
  int lane = tid & 31, warp = tid >> 5;
  int warpM = warp >> 1, warpN = warp & 1;
  int m0 = blockIdx.y * 128;
  int n0 = blockIdx.x * 128;
  int b = n0 / PIX;
  int pix0 = n0 - b * PIX;
  const float* Ap = g_wqkv;
  const float* Bp = g_x + (size_t)b * 256 * PIX + pix0;

  float acc[2][8][4];
  #pragma unroll
  for (int mt = 0; mt < 2; mt++)
    #pragma unroll
    for (int nt = 0; nt < 8; nt++)
      #pragma unroll
      for (int i = 0; i < 4; i++) acc[mt][nt][i] = 0.f;

  auto issue = [&](int s, int t){
    int k0 = t * 16;
    #pragma unroll
    for (int u = 0; u < 2; u++){
      int idx = tid + u * 256;
      int r = idx >> 2, c = (idx & 3) * 4;
      cp16(&Asm[s][r][c], Ap + (m0 + r) * 256 + k0 + c);
      int rb = idx >> 5, cb = (idx & 31) * 4;
      cp16(&Bsm[s][rb][cb], Bp + (size_t)(k0 + rb) * PIX + cb);
    }
  };
  issue(0, 0); CP_COMMIT();

  for (int t = 0; t < 16; t++){
    int cur = t & 1;
    if (t + 1 < 16) issue(1 - cur, t + 1);
    CP_COMMIT();
    CP_WAIT1();
    __syncthreads();
    #pragma unroll
    for (int kk = 0; kk < 16; kk += 8){
      uint32_t af[2][4], bf[8][2];
      int kr = kk + (lane & 3);
      #pragma unroll
      for (int mt = 0; mt < 2; mt++){
        int rb = warpM * 32 + mt * 16 + (lane >> 2);
        af[mt][0] = Asm[cur][rb    ][kr];
        af[mt][1] = Asm[cur][rb + 8][kr];
        af[mt][2] = Asm[cur][rb    ][kr + 4];
        af[mt][3] = Asm[cur][rb + 8][kr + 4];
      }
      #pragma unroll
      for (int nt = 0; nt < 8; nt++){
        int nb = warpN * 64 + nt * 8 + (lane >> 2);
        bf[nt][0] = Bsm[cur][kr    ][nb];
        bf[nt][1] = Bsm[cur][kr + 4][nb];
      }
      #pragma unroll
      for (int mt = 0; mt < 2; mt++)
        #pragma unroll
        for (int nt = 0; nt < 8; nt++)
          mma_tf32(acc[mt][nt], af[mt], bf[nt]);
    }
    __syncthreads();
  }
  float* outp = g_qkv + (size_t)b * 768 * PIX + pix0;
  #pragma unroll
  for (int mt = 0; mt < 2; mt++){
    #pragma unroll
    for (int ii = 0; ii < 2; ii++){
      int o = m0 + warpM * 32 + mt * 16 + (lane >> 2) + ii * 8;
      #pragma unroll
      for (int nt = 0; nt < 8; nt++){
        int col = warpN * 64 + nt * 8 + (lane & 3) * 2;
        float2 v = make_float2(acc[mt][nt][ii*2], acc[mt][nt][ii*2+1]);
        *(float2*)&outp[(size_t)o * PIX + col] = v;
      }
    }
  }
}

// ---------------- K2: per-group 10-token attention + LN + GELU (3568 baseline) ----------
__global__ __launch_bounds__(256) void k_attn1(const float* __restrict__ gamma,
                                               const float* __restrict__ beta){
  __shared__ float sq[6912];
  __shared__ float stok[768];
  __shared__ float sd[8][10][10];
  int gidx = blockIdx.x;
  int b = gidx >> 10, g = gidx & 1023;
  int gy = g >> 5, gx = g & 31;
  int tid = threadIdx.x;

  const float* src = g_qkv + (size_t)b * 768 * PIX + (gy * 3) * HWDIM + gx * 3;
  for (int i = tid; i < 6912; i += 256){
    int o = i / 9, win = i - o * 9;
    int r = win / 3, c = win - r * 3;
    sq[i] = src[(size_t)o * PIX + r * HWDIM + c];
  }
  for (int i = tid; i < 768; i += 256) stok[i] = g_tok[i];
  __syncthreads();

  int hh = tid >> 5, lane = tid & 31;
  int oq = hh * 32 + lane;

  float qr[10], kr[10], vr[10];
  qr[0] = stok[oq]; kr[0] = stok[oq + 256]; vr[0] = stok[oq + 512];
  #pragma unroll
  for (int n = 1; n < 10; n++){
    qr[n] = sq[oq * 9 + n - 1];
    kr[n] = sq[(oq + 256) * 9 + n - 1];
    vr[n] = sq[(oq + 512) * 9 + n - 1];
  }
  #pragma unroll
  for (int i = 0; i < 10; i++){
    #pragma unroll
    for (int j = 0; j < 10; j++){
      float t = allsum(qr[i] * kr[j]);
      if (lane == 0) sd[hh][i][j] = t * SCALE;
    }
  }
  __syncwarp();
  if (lane < 10){
    float row[10]; float m = -1e30f;
    #pragma unroll
    for (int j = 0; j < 10; j++){ row[j] = sd[hh][lane][j]; m = fmaxf(m, row[j]); }
    float s = 0.f;
    #pragma unroll
    for (int j = 0; j < 10; j++){ row[j] = fexp(row[j] - m); s += row[j]; }
    float inv = 1.f / s;
    #pragma unroll
    for (int j = 0; j < 10; j++) sd[hh][lane][j] = row[j] * inv;
  }
  __syncwarp();
  float x0 = 0.f;
  #pragma unroll
  for (int j = 0; j < 10; j++) x0 = fmaf(sd[hh][0][j], vr[j], x0);
  float mu = allsum(x0) * 0.03125f;
  float dv = x0 - mu;
  float var = allsum(dv * dv) * 0.03125f;
  float xn = dv * rsqrtf(var + 1e-5f) * gamma[lane] + beta[lane];
  float ge = 0.5f * xn * (1.f + erff(xn * 0.70710678118654752f));
  g_t[b * 262144 + oq * 1024 + g] = ge;

  size_t gfb = ((size_t)(b * 8 + hh) * NG + g) * 288 + lane;
  #pragma unroll
  for (int i = 1; i < 10; i++){
    float o = 0.f;
    #pragma unroll
    for (int j = 0; j < 10; j++) o = fmaf(sd[hh][i][j], vr[j], o);
    g_gf[gfb + (i - 1) * 32] = roundtf(o);   // pre-rounded for k_agg raw-bit consumption
  }
}

// ---------------- K3: qk GEMM (tf32) per-batch M=512,K=256,N=1024 (unchanged) -----------
__global__ __launch_bounds__(256) void k_qk(const float* __restrict__ A,
                                            const float* __restrict__ bias){
  __shared__ uint32_t As[16][132];
  __shared__ uint32_t Bs[16][132];
  int tid = threadIdx.x;
  int lane = tid & 31, warp = tid >> 5;
  int warpM = warp >> 1, warpN = warp & 1;
  int n0 = blockIdx.x * 128, m0 = blockIdx.y * 128, b = blockIdx.z;
  const float* Bp = g_t + b * 262144;

  float acc[2][8][4];
  #pragma unroll
  for (int mt = 0; mt < 2; mt++)
    #pragma unroll
    for (int nt = 0; nt < 8; nt++)
      #pragma unroll
      for (int i = 0; i < 4; i++) acc[mt][nt][i] = 0.f;

  int ar = tid >> 1, ac = (tid & 1) * 8;
  int br = tid >> 4, bc = (tid & 15) * 8;

  for (int k0 = 0; k0 < 256; k0 += 16){
    float4 a0 = *(const float4*)(A + (m0 + ar) * 256 + k0 + ac);
    float4 a1 = *(const float4*)(A + (m0 + ar) * 256 + k0 + ac + 4);
    As[ac+0][ar]=f2tf32(a0.x); As[ac+1][ar]=f2tf32(a0.y);
    As[ac+2][ar]=f2tf32(a0.z); As[ac+3][ar]=f2tf32(a0.w);
    As[ac+4][ar]=f2tf32(a1.x); As[ac+5][ar]=f2tf32(a1.y);
    As[ac+6][ar]=f2tf32(a1.z); As[ac+7][ar]=f2tf32(a1.w);
    float4 b0 = *(const float4*)(Bp + (k0 + br) * 1024 + n0 + bc);
    float4 b1 = *(const float4*)(Bp + (k0 + br) * 1024 + n0 + bc + 4);
    Bs[br][bc+0]=f2tf32(b0.x); Bs[br][bc+1]=f2tf32(b0.y);
    Bs[br][bc+2]=f2tf32(b0.z); Bs[br][bc+3]=f2tf32(b0.w);
    Bs[br][bc+4]=f2tf32(b1.x); Bs[br][bc+5]=f2tf32(b1.y);
    Bs[br][bc+6]=f2tf32(b1.z); Bs[br][bc+7]=f2tf32(b1.w);
    __syncthreads();
    #pragma unroll
    for (int kk = 0; kk < 16; kk += 8){
      uint32_t af[2][4], bf[8][2];
      int kr = kk + (lane & 3);
      #pragma unroll
      for (int mt = 0; mt < 2; mt++){
        int rb = warpM * 32 + mt * 16 + (lane >> 2);
        af[mt][0] = As[kr    ][rb];
        af[mt][1] = As[kr    ][rb + 8];
        af[mt][2] = As[kr + 4][rb];
        af[mt][3] = As[kr + 4][rb + 8];
      }
      #pragma unroll
      for (int nt = 0; nt < 8; nt++){
        int nb = warpN * 64 + nt * 8 + (lane >> 2);
        bf[nt][0] = Bs[kr    ][nb];
        bf[nt][1] = Bs[kr + 4][nb];
      }
      #pragma unroll
      for (int mt = 0; mt < 2; mt++)
        #pragma unroll
        for (int nt = 0; nt < 8; nt++)
          mma_tf32(acc[mt][nt], af[mt], bf[nt]);
    }
    __syncthreads();
  }
  #pragma unroll
  for (int mt = 0; mt < 2; mt++){
    #pragma unroll
    for (int ii = 0; ii < 2; ii++){
      int o = m0 + warpM * 32 + mt * 16 + (lane >> 2) + ii * 8;
      float bi = bias[o];
      int h = o >> 6, dd = o & 63;
      #pragma unroll
      for (int nt = 0; nt < 8; nt++){
        #pragma unroll
        for (int jj = 0; jj < 2; jj++){
          int n = n0 + warpN * 64 + nt * 8 + (lane & 3) * 2 + jj;
          float v = acc[mt][nt][ii * 2 + jj] + bi;
          if (dd < 32) g_wq[((b * 8 + h) * 1024 + n) * 32 + dd] = v;
          else         g_wkt[((b * 8 + h) * 32 + (dd - 32)) * 1024 + n] = v;
        }
      }
    }
  }
}

// ---------------- K4a: window dots (tf32) + rowmax (unchanged) ----------------
__global__ __launch_bounds__(256) void k_dots(){
  __shared__ uint32_t As[32][132];
  __shared__ uint32_t Bs[32][132];
  int tid = threadIdx.x;
  int lane = tid & 31, warp = tid >> 5;
  int warpM = warp >> 1, warpN = warp & 1;
  int bh = blockIdx.z;
  int m0 = blockIdx.y * 128, n0 = blockIdx.x * 128;
  const float* Ap = g_wq + bh * 32768;
  const float* Bp = g_wkt + bh * 32768;

  int ar = tid >> 1, ac = (tid & 1) * 16;
  #pragma unroll
  for (int i = 0; i < 16; i += 4){
    float4 v = *(const float4*)(Ap + (m0 + ar) * 32 + ac + i);
    As[ac+i+0][ar]=f2tf32(v.x); As[ac+i+1][ar]=f2tf32(v.y);
    As[ac+i+2][ar]=f2tf32(v.z); As[ac+i+3][ar]=f2tf32(v.w);
  }
  int br = tid >> 3, bc = (tid & 7) * 16;
  #pragma unroll
  for (int i = 0; i < 16; i += 4){
    float4 v = *(const float4*)(Bp + br * 1024 + n0 + bc + i);
    Bs[br][bc+i+0]=f2tf32(v.x); Bs[br][bc+i+1]=f2tf32(v.y);
    Bs[br][bc+i+2]=f2tf32(v.z); Bs[br][bc+i+3]=f2tf32(v.w);
  }
  __syncthreads();

  float acc[2][8][4];
  #pragma unroll
  for (int mt = 0; mt < 2; mt++)
    #pragma unroll
    for (int nt = 0; nt < 8; nt++)
      #pragma unroll
      for (int i = 0; i < 4; i++) acc[mt][nt][i] = 0.f;

  #pragma unroll
  for (int kk = 0; kk < 32; kk += 8){
    uint32_t af[2][4], bf[8][2];
    int kr = kk + (lane & 3);
    #pragma unroll
    for (int mt = 0; mt < 2; mt++){
      int rb = warpM * 32 + mt * 16 + (lane >> 2);
      af[mt][0] = As[kr    ][rb];
      af[mt][1] = As[kr    ][rb + 8];
      af[mt][2] = As[kr + 4][rb];
      af[mt][3] = As[kr + 4][rb + 8];
    }
    #pragma unroll
    for (int nt = 0; nt < 8; nt++){
      int nb = warpN * 64 + nt * 8 + (lane >> 2);
      bf[nt][0] = Bs[kr    ][nb];
      bf[nt][1] = Bs[kr + 4][nb];
    }
    #pragma unroll
    for (int mt = 0; mt < 2; mt++)
      #pragma unroll
      for (int nt = 0; nt < 8; nt++)
        mma_tf32(acc[mt][nt], af[mt], bf[nt]);
  }
  float* out = g_dots + (size_t)bh * 1048576;
  unsigned* rmx = g_rmax + bh * 1024;
  #pragma unroll
  for (int mt = 0; mt < 2; mt++){
    #pragma unroll
    for (int ii = 0; ii < 2; ii++){
      int row = m0 + warpM * 32 + mt * 16 + (lane >> 2) + ii * 8;
      float rmax = -1e30f;
      #pragma unroll
      for (int nt = 0; nt < 8; nt++){
        int col = n0 + warpN * 64 + nt * 8 + (lane & 3) * 2;
        float2 v = make_float2(acc[mt][nt][ii*2] * SCALE, acc[mt][nt][ii*2+1] * SCALE);
        rmax = fmaxf(rmax, fmaxf(v.x, v.y));
        *(float2*)&out[(size_t)row * 1024 + col] = v;
      }
      rmax = fmaxf(rmax, __shfl_xor_sync(0xffffffffu, rmax, 1));
      rmax = fmaxf(rmax, __shfl_xor_sync(0xffffffffu, rmax, 2));
      if ((lane & 3) == 0) atomicMax(&rmx[row], fenc(rmax));
    }
  }
}

// ---------------- K4b: exp pass — g_dots := roundtf(exp(v - rowmax)), row sums ----------
__global__ __launch_bounds__(256) void k_exp(){
  int row = blockIdx.x * 8 + (threadIdx.x >> 5);
  int lane = threadIdx.x & 31;
  float rmx = fdec(g_rmax[row]);
  float4* r = (float4*)(g_dots + (size_t)row * 1024);
  float s = 0.f;
  #pragma unroll
  for (int e = 0; e < 8; e++){
    float4 v = r[lane + e * 32];
    v.x = roundtf(fexp(v.x - rmx)); v.y = roundtf(fexp(v.y - rmx));
    v.z = roundtf(fexp(v.z - rmx)); v.w = roundtf(fexp(v.w - rmx));
    s += (v.x + v.y) + (v.z + v.w);
    r[lane + e * 32] = v;
  }
  s = allsum(s);
  if (lane == 0) g_rsum[row] = s;
}

// ---------------- K4c: agg GEMM (tf32, cp.async 2-stage) per (b,h): 1024x288x1024 -------
__global__ __launch_bounds__(256) void k_agg(){
  __shared__ __align__(16) uint32_t Asm[2][128][20];  // [m][k]
  __shared__ __align__(16) uint32_t Bsm[2][16][100];  // [k][n]
  int tid = threadIdx.x;
  int lane = tid & 31, warp = tid >> 5;
  int warpM = warp >> 1, warpN = warp & 1;
  int bh = blockIdx.z;
  int m0 = blockIdx.y * 128, n0 = blockIdx.x * 96;
  const float* Ap = g_dots + (size_t)bh * 1048576;
  const float* Bp = g_gf + (size_t)bh * 294912 + n0;

  float acc[2][6][4];
  #pragma unroll
  for (int mt = 0; mt < 2; mt++)
    #pragma unroll
    for (int nt = 0; nt < 6; nt++)
      #pragma unroll
      for (int i = 0; i < 4; i++) acc[mt][nt][i] = 0.f;

  auto issue = [&](int s, int t){
    int k0 = t * 16;
    #pragma unroll
    for (int u = 0; u < 2; u++){
      int idx = tid + u * 256;
      int r = idx >> 2, c = (idx & 3) * 4;
      cp16(&Asm[s][r][c], Ap + (size_t)(m0 + r) * 1024 + k0 + c);
    }
    {
      int idx = tid;
      int r = idx / 24, c = (idx % 24) * 4;
      cp16(&Bsm[s][r][c], Bp + (size_t)(k0 + r) * 288 + c);
      if (tid < 128){
        idx = tid + 256;
        r = idx / 24; c = (idx % 24) * 4;
        cp16(&Bsm[s][r][c], Bp + (size_t)(k0 + r) * 288 + c);
      }
    }
  };
  issue(0, 0); CP_COMMIT();

  for (int t = 0; t < 64; t++){
    int cur = t & 1;
    if (t + 1 < 64) issue(1 - cur, t + 1);
    CP_COMMIT();
    CP_WAIT1();
    __syncthreads();
    #pragma unroll
    for (int kk = 0; kk < 16; kk += 8){
      uint32_t af[2][4], bf[6][2];
      int kr = kk + (lane & 3);
      #pragma unroll
      for (int mt = 0; mt < 2; mt++){
        int rb = warpM * 32 + mt * 16 + (lane >> 2);
        af[mt][0] = Asm[cur][rb    ][kr];
        af[mt][1] = Asm[cur][rb + 8][kr];
        af[mt][2] = Asm[cur][rb    ][kr + 4];
        af[mt][3] = Asm[cur][rb + 8][kr + 4];
      }
      #pragma unroll
      for (int nt = 0; nt < 6; nt++){
        int nb = warpN * 48 + nt * 8 + (lane >> 2);
        bf[nt][0] = Bsm[cur][kr    ][nb];
        bf[nt][1] = Bsm[cur][kr + 4][nb];
      }
      #pragma unroll
      for (int mt = 0; mt < 2; mt++)
        #pragma unroll
        for (int nt = 0; nt < 6; nt++)
          mma_tf32(acc[mt][nt], af[mt], bf[nt]);
    }
    __syncthreads();
  }
  float* out = g_agg + (size_t)bh * 294912;
  const float* rs = g_rsum + bh * 1024 + m0;
  #pragma unroll
  for (int mt = 0; mt < 2; mt++){
    #pragma unroll
    for (int ii = 0; ii < 2; ii++){
      int rl = warpM * 32 + mt * 16 + (lane >> 2) + ii * 8;
      float inv = 1.f / rs[rl];
      int row = m0 + rl;
      #pragma unroll
      for (int nt = 0; nt < 6; nt++){
        int col = n0 + warpN * 48 + nt * 8 + (lane & 3) * 2;
        out[(size_t)row * 288 + col    ] = roundtf(acc[mt][nt][ii * 2    ] * inv);
        out[(size_t)row * 288 + col + 1] = roundtf(acc[mt][nt][ii * 2 + 1] * inv);
      }
    }
  }
}

// ---------------- K5: output projection (tf32, cp.async 2-stage) ------------------------
__global__ __launch_bounds__(256) void k_out(const float* __restrict__ bias,
                                             float* __restrict__ out){
  __shared__ __align__(16) uint32_t Asm[2][128][20];  // [m][k]
  __shared__ __align__(16) uint32_t Bsm[2][128][20];  // [n][k]
  int tid = threadIdx.x;
  int lane = tid & 31, warp = tid >> 5;
  int warpM = warp >> 1, warpN = warp & 1;
  int n0 = blockIdx.x * 128, m0 = blockIdx.y * 128;
  int b = n0 / PIX;
  int pix0 = n0 - b * PIX;

  int nb = tid & 127;
  int kh = tid >> 7;
  int pix = pix0 + nb;
  int y = pix / HWDIM, xc = pix - y * HWDIM;
  int g = (y / 3) * 32 + xc / 3;
  int win = (y % 3) * 3 + (xc % 3);
  size_t colbase = (size_t)b * 2359296 + (size_t)g * 288 + win * 32 + kh * 8;
  int kb = kh * 8;

  float acc[2][8][4];
  #pragma unroll
  for (int mt = 0; mt < 2; mt++)
    #pragma unroll
    for (int nt = 0; nt < 8; nt++)
      #pragma unroll
      for (int i = 0; i < 4; i++) acc[mt][nt][i] = 0.f;

  auto issue = [&](int s, int t){
    int k0 = t * 16;
    #pragma unroll
    for (int u = 0; u < 2; u++){
      int idx = tid + u * 256;
      int r = idx >> 2, c = (idx & 3) * 4;
      cp16(&Asm[s][r][c], g_wo + (m0 + r) * 256 + k0 + c);
    }
    const float* bsrc = g_agg + colbase + (size_t)(t >> 1) * 294912 + (t & 1) * 16;
    cp16(&Bsm[s][nb][kb], bsrc);
    cp16(&Bsm[s][nb][kb + 4], bsrc + 4);
  };
  issue(0, 0); CP_COMMIT();

  for (int t = 0; t < 16; t++){
    int cur = t & 1;
    if (t + 1 < 16) issue(1 - cur, t + 1);
    CP_COMMIT();
    CP_WAIT1();
    __syncthreads();
    #pragma unroll
    for (int kk = 0; kk < 16; kk += 8){
      uint32_t af[2][4], bf[8][2];
      int kr = kk + (lane & 3);
      #pragma unroll
      for (int mt = 0; mt < 2; mt++){
        int rb = warpM * 32 + mt * 16 + (lane >> 2);
        af[mt][0] = Asm[cur][rb    ][kr];
        af[mt][1] = Asm[cur][rb + 8][kr];
        af[mt][2] = Asm[cur][rb    ][kr + 4];
        af[mt][3] = Asm[cur][rb + 8][kr + 4];
      }
      #pragma unroll
      for (int nt = 0; nt < 8; nt++){
        int nbc = warpN * 64 + nt * 8 + (lane >> 2);
        bf[nt][0] = Bsm[cur][nbc][kr];
        bf[nt][1] = Bsm[cur][nbc][kr + 4];
      }
      #pragma unroll
      for (int mt = 0; mt < 2; mt++)
        #pragma unroll
        for (int nt = 0; nt < 8; nt++)
          mma_tf32(acc[mt][nt], af[mt], bf[nt]);
    }
    __syncthreads();
  }
  float* op = out + ((size_t)b * 256) * PIX + pix0;
  #pragma unroll
  for (int mt = 0; mt < 2; mt++){
    #pragma unroll
    for (int ii = 0; ii < 2; ii++){
      int o = m0 + warpM * 32 + mt * 16 + (lane >> 2) + ii * 8;
      float bi = bias[o];
      #pragma unroll
      for (int nt = 0; nt < 8; nt++){
        int col = warpN * 64 + nt * 8 + (lane & 3) * 2;
        float2 v = make_float2(acc[mt][nt][ii*2] + bi, acc[mt][nt][ii*2+1] + bi);
        *(float2*)&op[(size_t)o * PIX + col] = v;
      }
    }
  }
}

// ---------------- launch ----------------
extern "C" void kernel_launch(void* const* d_in, const int* in_sizes, int n_in,
                              void* d_out, int out_size){
  const float* x      = (const float*)d_in[0];
  const float* w_qkv  = (const float*)d_in[1];
  const float* gtok   = (const float*)d_in[2];
  const float* gamma  = (const float*)d_in[3];
  const float* beta   = (const float*)d_in[4];
  const float* w_qk   = (const float*)d_in[5];
  const float* b_qk   = (const float*)d_in[6];
  const float* w_out  = (const float*)d_in[7];
  const float* b_out  = (const float*)d_in[8];
  float* out = (float*)d_out;

  float* d_gx; cudaGetSymbolAddress((void**)&d_gx, g_x);
  float* d_gw; cudaGetSymbolAddress((void**)&d_gw, g_wqkv);
  float* d_go; cudaGetSymbolAddress((void**)&d_go, g_wo);

  k_zero <<<128, 256>>>();
  k_round<<<36864, 256>>>(d_gx, x, 9437184);
  k_round<<<192,   256>>>(d_gw, w_qkv, 49152);
  k_round<<<64,    256>>>(d_go, w_out, 16384);
  k_tok  <<<3, 256>>>(w_qkv, gtok);
  k_qkv  <<<dim3(1152, 6), 256>>>();
  k_attn1<<<16384, 256>>>(gamma, beta);
  k_qk   <<<dim3(8, 4, 16), 256>>>(w_qk, b_qk);
  k_dots <<<dim3(8, 8, 128), 256>>>();
  k_exp  <<<16384, 256>>>();
  k_agg  <<<dim3(3, 8, 128), 256>>>();
  k_out  <<<dim3(1152, 2), 256>>>(b_out, out);
}

// round 16
// speedup vs baseline: 1.9170x; 1.0804x over previous
#include <cuda_runtime.h>
#include <cstdint>

// ---------------- problem constants ----------------
#define HWDIM 96
#define PIX   9216
#define NG    1024
#define SCALE 0.17677669529663687f

// ---------------- scratch ----------------
__device__ float g_qkv[113246208];   // [b][768][9216]
__device__ float g_tok[768];
__device__ float g_t[4194304];       // [b][256][1024]
__device__ float g_gf[37748736];     // [(b*8+h)*1024+g][9][32]  (tf32-rounded)
__device__ float g_wq[4194304];
__device__ float g_wkt[4194304];
__device__ float g_dots[134217728];  // exp'd, tf32-rounded probabilities (unnormalized)
__device__ float g_rsum[131072];     // per-row sum of exp
__device__ float g_agg[37748736];    // tf32-rounded
__device__ float g_x[37748736];      // tf32-rounded x
__device__ float g_wqkv[196608];     // tf32-rounded w_qkv
__device__ float g_wo[65536];        // tf32-rounded w_out

__device__ __forceinline__ float allsum(float v){
  #pragma unroll
  for (int o = 16; o > 0; o >>= 1) v += __shfl_xor_sync(0xffffffffu, v, o);
  return v;
}
// FFMA-only exp, clamped to [-80, 80]. Logits here are |x| <~ 0.5 by construction.
__device__ __forceinline__ float fexp(float x){
  x = fmaxf(fminf(x, 80.f), -80.f);
  float t = fmaf(x, 1.4426950408889634f, 12582912.f);
  int e = __float_as_int(t) << 23;
  float i = t - 12582912.f;
  float f = fmaf(x, 1.4426950408889634f, -i);
  float p =       1.3333558e-3f;
  p = fmaf(p, f, 9.6181291e-3f);
  p = fmaf(p, f, 5.5504109e-2f);
  p = fmaf(p, f, 2.4022651e-1f);
  p = fmaf(p, f, 6.9314718e-1f);
  p = fmaf(p, f, 1.0f);
  return __int_as_float(__float_as_int(p) + e);
}
__device__ __forceinline__ uint32_t f2tf32(float v){
  uint32_t t;
  asm("cvt.rna.tf32.f32 %0, %1;" : "=r"(t) : "f"(v));
  return t;
}
__device__ __forceinline__ float roundtf(float v){ return __uint_as_float(f2tf32(v)); }
__device__ __forceinline__ void mma_tf32(float* d, const uint32_t* a, const uint32_t* b){
  asm volatile(
    "mma.sync.aligned.m16n8k8.row.col.f32.tf32.tf32.f32 "
    "{%0,%1,%2,%3}, {%4,%5,%6,%7}, {%8,%9}, {%0,%1,%2,%3};\n"
    : "+f"(d[0]), "+f"(d[1]), "+f"(d[2]), "+f"(d[3])
    : "r"(a[0]), "r"(a[1]), "r"(a[2]), "r"(a[3]), "r"(b[0]), "r"(b[1]));
}
__device__ __forceinline__ void cp16(void* smem, const void* gmem){
  uint32_t s = (uint32_t)__cvta_generic_to_shared(smem);
  asm volatile("cp.async.cg.shared.global [%0], [%1], 16;\n" :: "r"(s), "l"(gmem));
}
#define CP_COMMIT() asm volatile("cp.async.commit_group;\n")
#define CP_WAIT1()  asm volatile("cp.async.wait_group 1;\n")

// ---------------- utility kernels ----------------
__global__ void k_zero(){
  ((uint4*)g_rsum)[blockIdx.x * 256 + threadIdx.x] = make_uint4(0,0,0,0);
}
__global__ void k_round(float* __restrict__ dst, const float* __restrict__ src, int n4){
  int i = blockIdx.x * 256 + threadIdx.x;
  if (i < n4){
    float4 v = ((const float4*)src)[i];
    v.x = roundtf(v.x); v.y = roundtf(v.y); v.z = roundtf(v.z); v.w = roundtf(v.w);
    ((float4*)dst)[i] = v;
  }
}
__global__ void k_tok(const float* __restrict__ w, const float* __restrict__ tok){
  int o = blockIdx.x * 256 + threadIdx.x;
  if (o < 768){
    const float* wr = w + o * 256;
    float s = 0.f;
    #pragma unroll 8
    for (int c = 0; c < 256; c++) s += wr[c] * tok[c];
    g_tok[o] = s;
  }
}

// ---------------- K1: qkv GEMM (tf32, cp.async 2-stage)  M=768,K=256,N=147456 -----------
__global__ __launch_bounds__(256) void k_qkv(){
  __shared__ __align__(16) uint32_t Asm[2][128][20];
  __shared__ __align__(16) uint32_t Bsm[2][16][132];
  int tid = threadIdx.x;
  int lane = tid & 31, warp = tid >> 5;
  int warpM = warp >> 1, warpN = warp & 1;
  int m0 = blockIdx.y * 128;
  int n0 = blockIdx.x * 128;
  int b = n0 / PIX;
  int pix0 = n0 - b * PIX;
  const float* Ap = g_wqkv;
  const float* Bp = g_x + (size_t)b * 256 * PIX + pix0;

  float acc[2][8][4];
  #pragma unroll
  for (int mt = 0; mt < 2; mt++)
    #pragma unroll
    for (int nt = 0; nt < 8; nt++)
      #pragma unroll
      for (int i = 0; i < 4; i++) acc[mt][nt][i] = 0.f;

  auto issue = [&](int s, int t){
    int k0 = t * 16;
    #pragma unroll
    for (int u = 0; u < 2; u++){
      int idx = tid + u * 256;
      int r = idx >> 2, c = (idx & 3) * 4;
      cp16(&Asm[s][r][c], Ap + (m0 + r) * 256 + k0 + c);
      int rb = idx >> 5, cb = (idx & 31) * 4;
      cp16(&Bsm[s][rb][cb], Bp + (size_t)(k0 + rb) * PIX + cb);
    }
  };
  issue(0, 0); CP_COMMIT();

  for (int t = 0; t < 16; t++){
    int cur = t & 1;
    if (t + 1 < 16) issue(1 - cur, t + 1);
    CP_COMMIT();
    CP_WAIT1();
    __syncthreads();
    #pragma unroll
    for (int kk = 0; kk < 16; kk += 8){
      uint32_t af[2][4], bf[8][2];
      int kr = kk + (lane & 3);
      #pragma unroll
      for (int mt = 0; mt < 2; mt++){
        int rb = warpM * 32 + mt * 16 + (lane >> 2);
        af[mt][0] = Asm[cur][rb    ][kr];
        af[mt][1] = Asm[cur][rb + 8][kr];
        af[mt][2] = Asm[cur][rb    ][kr + 4];
        af[mt][3] = Asm[cur][rb + 8][kr + 4];
      }
      #pragma unroll
      for (int nt = 0; nt < 8; nt++){
        int nb = warpN * 64 + nt * 8 + (lane >> 2);
        bf[nt][0] = Bsm[cur][kr    ][nb];
        bf[nt][1] = Bsm[cur][kr + 4][nb];
      }
      #pragma unroll
      for (int mt = 0; mt < 2; mt++)
        #pragma unroll
        for (int nt = 0; nt < 8; nt++)
          mma_tf32(acc[mt][nt], af[mt], bf[nt]);
    }
    __syncthreads();
  }
  float* outp = g_qkv + (size_t)b * 768 * PIX + pix0;
  #pragma unroll
  for (int mt = 0; mt < 2; mt++){
    #pragma unroll
    for (int ii = 0; ii < 2; ii++){
      int o = m0 + warpM * 32 + mt * 16 + (lane >> 2) + ii * 8;
      #pragma unroll
      for (int nt = 0; nt < 8; nt++){
        int col = warpN * 64 + nt * 8 + (lane & 3) * 2;
        float2 v = make_float2(acc[mt][nt][ii*2], acc[mt][nt][ii*2+1]);
        *(float2*)&outp[(size_t)o * PIX + col] = v;
      }
    }
  }
}

// ---------------- K2: per-group attention + LN + GELU (coalesced multi-group) -----------
// block = (b, gy, gx-tile of 4, head-half of 4). smem [o(384)][gl(4)*10+win], stride 41.
__global__ __launch_bounds__(256) void k_attn1(const float* __restrict__ gamma,
                                               const float* __restrict__ beta){
  extern __shared__ float sm[];            // 384 * 41 floats = 63 KB
  __shared__ float sd[8][10][11];
  int tid = threadIdx.x;
  int blk = blockIdx.x;
  int hh  = blk & 1;
  int gxt = (blk >> 1) & 7;
  int gy  = (blk >> 4) & 31;
  int b   = blk >> 9;

  // coalesced load: 48B runs (3 float4 per (o,row))
  const float4* base4 = (const float4*)(g_qkv + (size_t)b * 768 * PIX + gy * 288 + gxt * 12);
  for (int idx = tid; idx < 3456; idx += 256){
    int o = idx / 9, rem = idx - o * 9;
    int r = rem / 3, c4 = rem - r * 3;
    int orow = (o >> 7) * 256 + hh * 128 + (o & 127);
    float4 v = base4[(size_t)orow * 2304 + r * 24 + c4];
    int cc = c4 * 4;
    #pragma unroll
    for (int j = 0; j < 4; j++){
      int c = cc + j;
      int gl = c / 3, w = r * 3 + (c - gl * 3);
      sm[o * 41 + gl * 10 + 1 + w] = (&v.x)[j];
    }
  }
  for (int i = tid; i < 1536; i += 256){
    int o = i >> 2, gl = i & 3;
    sm[o * 41 + gl * 10] = g_tok[(o >> 7) * 256 + hh * 128 + (o & 127)];
  }
  __syncthreads();

  int warp = tid >> 5, lane = tid & 31;
  for (int it = 0; it < 2; it++){
    int t = warp * 2 + it;
    int hl = t >> 2, gl = t & 3;
    int qb = (hl * 32 + lane) * 41 + gl * 10;
    int kb = ((128 + hl * 32) + lane) * 41 + gl * 10;
    int vb = ((256 + hl * 32) + lane) * 41 + gl * 10;
    float qr[10], kr[10], vr[10];
    #pragma unroll
    for (int n = 0; n < 10; n++){
      qr[n] = sm[qb + n]; kr[n] = sm[kb + n]; vr[n] = sm[vb + n];
    }
    #pragma unroll
    for (int i = 0; i < 10; i++){
      #pragma unroll
      for (int j = 0; j < 10; j++){
        float s = allsum(qr[i] * kr[j]);
        if (lane == 0) sd[warp][i][j] = s * SCALE;
      }
    }
    __syncwarp();
    if (lane < 10){
      float row[10]; float m = -1e30f;
      #pragma unroll
      for (int j = 0; j < 10; j++){ row[j] = sd[warp][lane][j]; m = fmaxf(m, row[j]); }
      float s = 0.f;
      #pragma unroll
      for (int j = 0; j < 10; j++){ row[j] = fexp(row[j] - m); s += row[j]; }
      float inv = 1.f / s;
      #pragma unroll
      for (int j = 0; j < 10; j++) sd[warp][lane][j] = row[j] * inv;
    }
    __syncwarp();

    int h = hh * 4 + hl;
    int g = gy * 32 + gxt * 4 + gl;
    float x0 = 0.f;
    #pragma unroll
    for (int j = 0; j < 10; j++) x0 = fmaf(sd[warp][0][j], vr[j], x0);
    float mu = allsum(x0) * 0.03125f;
    float dv = x0 - mu;
    float var = allsum(dv * dv) * 0.03125f;
    float xn = dv * rsqrtf(var + 1e-5f) * gamma[lane] + beta[lane];
    float ge = 0.5f * xn * (1.f + erff(xn * 0.70710678118654752f));
    g_t[b * 262144 + (h * 32 + lane) * 1024 + g] = ge;

    size_t gfb = ((size_t)(b * 8 + h) * NG + g) * 288 + lane;
    #pragma unroll
    for (int i = 1; i < 10; i++){
      float o = 0.f;
      #pragma unroll
      for (int j = 0; j < 10; j++) o = fmaf(sd[warp][i][j], vr[j], o);
      g_gf[gfb + (i - 1) * 32] = roundtf(o);
    }
    __syncwarp();
  }
}

// ---------------- K3: qk GEMM (tf32) per-batch M=512,K=256,N=1024 -----------------------
__global__ __launch_bounds__(256) void k_qk(const float* __restrict__ A,
                                            const float* __restrict__ bias){
  __shared__ uint32_t As[16][132];
  __shared__ uint32_t Bs[16][132];
  int tid = threadIdx.x;
  int lane = tid & 31, warp = tid >> 5;
  int warpM = warp >> 1, warpN = warp & 1;
  int n0 = blockIdx.x * 128, m0 = blockIdx.y * 128, b = blockIdx.z;
  const float* Bp = g_t + b * 262144;

  float acc[2][8][4];
  #pragma unroll
  for (int mt = 0; mt < 2; mt++)
    #pragma unroll
    for (int nt = 0; nt < 8; nt++)
      #pragma unroll
      for (int i = 0; i < 4; i++) acc[mt][nt][i] = 0.f;

  int ar = tid >> 1, ac = (tid & 1) * 8;
  int br = tid >> 4, bc = (tid & 15) * 8;

  for (int k0 = 0; k0 < 256; k0 += 16){
    float4 a0 = *(const float4*)(A + (m0 + ar) * 256 + k0 + ac);
    float4 a1 = *(const float4*)(A + (m0 + ar) * 256 + k0 + ac + 4);
    As[ac+0][ar]=f2tf32(a0.x); As[ac+1][ar]=f2tf32(a0.y);
    As[ac+2][ar]=f2tf32(a0.z); As[ac+3][ar]=f2tf32(a0.w);
    As[ac+4][ar]=f2tf32(a1.x); As[ac+5][ar]=f2tf32(a1.y);
    As[ac+6][ar]=f2tf32(a1.z); As[ac+7][ar]=f2tf32(a1.w);
    float4 b0 = *(const float4*)(Bp + (k0 + br) * 1024 + n0 + bc);
    float4 b1 = *(const float4*)(Bp + (k0 + br) * 1024 + n0 + bc + 4);
    Bs[br][bc+0]=f2tf32(b0.x); Bs[br][bc+1]=f2tf32(b0.y);
    Bs[br][bc+2]=f2tf32(b0.z); Bs[br][bc+3]=f2tf32(b0.w);
    Bs[br][bc+4]=f2tf32(b1.x); Bs[br][bc+5]=f2tf32(b1.y);
    Bs[br][bc+6]=f2tf32(b1.z); Bs[br][bc+7]=f2tf32(b1.w);
    __syncthreads();
    #pragma unroll
    for (int kk = 0; kk < 16; kk += 8){
      uint32_t af[2][4], bf[8][2];
      int kr = kk + (lane & 3);
      #pragma unroll
      for (int mt = 0; mt < 2; mt++){
        int rb = warpM * 32 + mt * 16 + (lane >> 2);
        af[mt][0] = As[kr    ][rb];
        af[mt][1] = As[kr    ][rb + 8];
        af[mt][2] = As[kr + 4][rb];
        af[mt][3] = As[kr + 4][rb + 8];
      }
      #pragma unroll
      for (int nt = 0; nt < 8; nt++){
        int nb = warpN * 64 + nt * 8 + (lane >> 2);
        bf[nt][0] = Bs[kr    ][nb];
        bf[nt][1] = Bs[kr + 4][nb];
      }
      #pragma unroll
      for (int mt = 0; mt < 2; mt++)
        #pragma unroll
        for (int nt = 0; nt < 8; nt++)
          mma_tf32(acc[mt][nt], af[mt], bf[nt]);
    }
    __syncthreads();
  }
  #pragma unroll
  for (int mt = 0; mt < 2; mt++){
    #pragma unroll
    for (int ii = 0; ii < 2; ii++){
      int o = m0 + warpM * 32 + mt * 16 + (lane >> 2) + ii * 8;
      float bi = bias[o];
      int h = o >> 6, dd = o & 63;
      #pragma unroll
      for (int nt = 0; nt < 8; nt++){
        #pragma unroll
        for (int jj = 0; jj < 2; jj++){
          int n = n0 + warpN * 64 + nt * 8 + (lane & 3) * 2 + jj;
          float v = acc[mt][nt][ii * 2 + jj] + bi;
          if (dd < 32) g_wq[((b * 8 + h) * 1024 + n) * 32 + dd] = v;
          else         g_wkt[((b * 8 + h) * 32 + (dd - 32)) * 1024 + n] = v;
        }
      }
    }
  }
}

// ---------------- K4a: window dots (tf32) + fused exp + row-sum atomics -----------------
// logits are tiny (|x| <~ 0.5): exp without max-subtraction is exactly safe.
__global__ __launch_bounds__(256) void k_dots(){
  __shared__ uint32_t As[32][132];
  __shared__ uint32_t Bs[32][132];
  int tid = threadIdx.x;
  int lane = tid & 31, warp = tid >> 5;
  int warpM = warp >> 1, warpN = warp & 1;
  int bh = blockIdx.z;
  int m0 = blockIdx.y * 128, n0 = blockIdx.x * 128;
  const float* Ap = g_wq + bh * 32768;
  const float* Bp = g_wkt + bh * 32768;

  int ar = tid >> 1, ac = (tid & 1) * 16;
  #pragma unroll
  for (int i = 0; i < 16; i += 4){
    float4 v = *(const float4*)(Ap + (m0 + ar) * 32 + ac + i);
    As[ac+i+0][ar]=f2tf32(v.x); As[ac+i+1][ar]=f2tf32(v.y);
    As[ac+i+2][ar]=f2tf32(v.z); As[ac+i+3][ar]=f2tf32(v.w);
  }
  int br = tid >> 3, bc = (tid & 7) * 16;
  #pragma unroll
  for (int i = 0; i < 16; i += 4){
    float4 v = *(const float4*)(Bp + br * 1024 + n0 + bc + i);
    Bs[br][bc+i+0]=f2tf32(v.x); Bs[br][bc+i+1]=f2tf32(v.y);
    Bs[br][bc+i+2]=f2tf32(v.z); Bs[br][bc+i+3]=f2tf32(v.w);
  }
  __syncthreads();

  float acc[2][8][4];
  #pragma unroll
  for (int mt = 0; mt < 2; mt++)
    #pragma unroll
    for (int nt = 0; nt < 8; nt++)
      #pragma unroll
      for (int i = 0; i < 4; i++) acc[mt][nt][i] = 0.f;

  #pragma unroll
  for (int kk = 0; kk < 32; kk += 8){
    uint32_t af[2][4], bf[8][2];
    int kr = kk + (lane & 3);
    #pragma unroll
    for (int mt = 0; mt < 2; mt++){
      int rb = warpM * 32 + mt * 16 + (lane >> 2);
      af[mt][0] = As[kr    ][rb];
      af[mt][1] = As[kr    ][rb + 8];
      af[mt][2] = As[kr + 4][rb];
      af[mt][3] = As[kr + 4][rb + 8];
    }
    #pragma unroll
    for (int nt = 0; nt < 8; nt++){
      int nb = warpN * 64 + nt * 8 + (lane >> 2);
      bf[nt][0] = Bs[kr    ][nb];
      bf[nt][1] = Bs[kr + 4][nb];
    }
    #pragma unroll
    for (int mt = 0; mt < 2; mt++)
      #pragma unroll
      for (int nt = 0; nt < 8; nt++)
        mma_tf32(acc[mt][nt], af[mt], bf[nt]);
  }
  float* out = g_dots + (size_t)bh * 1048576;
  float* rs = g_rsum + bh * 1024;
  #pragma unroll
  for (int mt = 0; mt < 2; mt++){
    #pragma unroll
    for (int ii = 0; ii < 2; ii++){
      int row = m0 + warpM * 32 + mt * 16 + (lane >> 2) + ii * 8;
      float psum = 0.f;
      #pragma unroll
      for (int nt = 0; nt < 8; nt++){
        int col = n0 + warpN * 64 + nt * 8 + (lane & 3) * 2;
        float2 v;
        v.x = roundtf(fexp(acc[mt][nt][ii*2    ] * SCALE));
        v.y = roundtf(fexp(acc[mt][nt][ii*2 + 1] * SCALE));
        psum += v.x + v.y;
        *(float2*)&out[(size_t)row * 1024 + col] = v;
      }
      psum += __shfl_xor_sync(0xffffffffu, psum, 1);
      psum += __shfl_xor_sync(0xffffffffu, psum, 2);
      if ((lane & 3) == 0) atomicAdd(&rs[row], psum);
    }
  }
}

// ---------------- K4c: agg GEMM (tf32, cp.async 2-stage) per (b,h): 1024x288x1024 -------
__global__ __launch_bounds__(256) void k_agg(){
  __shared__ __align__(16) uint32_t Asm[2][128][20];
  __shared__ __align__(16) uint32_t Bsm[2][16][100];
  int tid = threadIdx.x;
  int lane = tid & 31, warp = tid >> 5;
  int warpM = warp >> 1, warpN = warp & 1;
  int bh = blockIdx.z;
  int m0 = blockIdx.y * 128, n0 = blockIdx.x * 96;
  const float* Ap = g_dots + (size_t)bh * 1048576;
  const float* Bp = g_gf + (size_t)bh * 294912 + n0;

  float acc[2][6][4];
  #pragma unroll
  for (int mt = 0; mt < 2; mt++)
    #pragma unroll
    for (int nt = 0; nt < 6; nt++)
      #pragma unroll
      for (int i = 0; i < 4; i++) acc[mt][nt][i] = 0.f;

  auto issue = [&](int s, int t){
    int k0 = t * 16;
    #pragma unroll
    for (int u = 0; u < 2; u++){
      int idx = tid + u * 256;
      int r = idx >> 2, c = (idx & 3) * 4;
      cp16(&Asm[s][r][c], Ap + (size_t)(m0 + r) * 1024 + k0 + c);
    }
    {
      int idx = tid;
      int r = idx / 24, c = (idx % 24) * 4;
      cp16(&Bsm[s][r][c], Bp + (size_t)(k0 + r) * 288 + c);
      if (tid < 128){
        idx = tid + 256;
        r = idx / 24; c = (idx % 24) * 4;
        cp16(&Bsm[s][r][c], Bp + (size_t)(k0 + r) * 288 + c);
      }
    }
  };
  issue(0, 0); CP_COMMIT();

  for (int t = 0; t < 64; t++){
    int cur = t & 1;
    if (t + 1 < 64) issue(1 - cur, t + 1);
    CP_COMMIT();
    CP_WAIT1();
    __syncthreads();
    #pragma unroll
    for (int kk = 0; kk < 16; kk += 8){
      uint32_t af[2][4], bf[6][2];
      int kr = kk + (lane & 3);
      #pragma unroll
      for (int mt = 0; mt < 2; mt++){
        int rb = warpM * 32 + mt * 16 + (lane >> 2);
        af[mt][0] = Asm[cur][rb    ][kr];
        af[mt][1] = Asm[cur][rb + 8][kr];
        af[mt][2] = Asm[cur][rb    ][kr + 4];
        af[mt][3] = Asm[cur][rb + 8][kr + 4];
      }
      #pragma unroll
      for (int nt = 0; nt < 6; nt++){
        int nb = warpN * 48 + nt * 8 + (lane >> 2);
        bf[nt][0] = Bsm[cur][kr    ][nb];
        bf[nt][1] = Bsm[cur][kr + 4][nb];
      }
      #pragma unroll
      for (int mt = 0; mt < 2; mt++)
        #pragma unroll
        for (int nt = 0; nt < 6; nt++)
          mma_tf32(acc[mt][nt], af[mt], bf[nt]);
    }
    __syncthreads();
  }
  float* out = g_agg + (size_t)bh * 294912;
  const float* rs = g_rsum + bh * 1024 + m0;
  #pragma unroll
  for (int mt = 0; mt < 2; mt++){
    #pragma unroll
    for (int ii = 0; ii < 2; ii++){
      int rl = warpM * 32 + mt * 16 + (lane >> 2) + ii * 8;
      float inv = 1.f / rs[rl];
      int row = m0 + rl;
      #pragma unroll
      for (int nt = 0; nt < 6; nt++){
        int col = n0 + warpN * 48 + nt * 8 + (lane & 3) * 2;
        out[(size_t)row * 288 + col    ] = roundtf(acc[mt][nt][ii * 2    ] * inv);
        out[(size_t)row * 288 + col + 1] = roundtf(acc[mt][nt][ii * 2 + 1] * inv);
      }
    }
  }
}

// ---------------- K5: output projection (tf32, cp.async 2-stage) ------------------------
__global__ __launch_bounds__(256) void k_out(const float* __restrict__ bias,
                                             float* __restrict__ out){
  __shared__ __align__(16) uint32_t Asm[2][128][20];
  __shared__ __align__(16) uint32_t Bsm[2][128][20];
  int tid = threadIdx.x;
  int lane = tid & 31, warp = tid >> 5;
  int warpM = warp >> 1, warpN = warp & 1;
  int n0 = blockIdx.x * 128, m0 = blockIdx.y * 128;
  int b = n0 / PIX;
  int pix0 = n0 - b * PIX;

  int nb = tid & 127;
  int kh = tid >> 7;
  int pix = pix0 + nb;
  int y = pix / HWDIM, xc = pix - y * HWDIM;
  int g = (y / 3) * 32 + xc / 3;
  int win = (y % 3) * 3 + (xc % 3);
  size_t colbase = (size_t)b * 2359296 + (size_t)g * 288 + win * 32 + kh * 8;
  int kb = kh * 8;

  float acc[2][8][4];
  #pragma unroll
  for (int mt = 0; mt < 2; mt++)
    #pragma unroll
    for (int nt = 0; nt < 8; nt++)
      #pragma unroll
      for (int i = 0; i < 4; i++) acc[mt][nt][i] = 0.f;

  auto issue = [&](int s, int t){
    int k0 = t * 16;
    #pragma unroll
    for (int u = 0; u < 2; u++){
      int idx = tid + u * 256;
      int r = idx >> 2, c = (idx & 3) * 4;
      cp16(&Asm[s][r][c], g_wo + (m0 + r) * 256 + k0 + c);
    }
    const float* bsrc = g_agg + colbase + (size_t)(t >> 1) * 294912 + (t & 1) * 16;
    cp16(&Bsm[s][nb][kb], bsrc);
    cp16(&Bsm[s][nb][kb + 4], bsrc + 4);
  };
  issue(0, 0); CP_COMMIT();

  for (int t = 0; t < 16; t++){
    int cur = t & 1;
    if (t + 1 < 16) issue(1 - cur, t + 1);
    CP_COMMIT();
    CP_WAIT1();
    __syncthreads();
    #pragma unroll
    for (int kk = 0; kk < 16; kk += 8){
      uint32_t af[2][4], bf[8][2];
      int kr = kk + (lane & 3);
      #pragma unroll
      for (int mt = 0; mt < 2; mt++){
        int rb = warpM * 32 + mt * 16 + (lane >> 2);
        af[mt][0] = Asm[cur][rb    ][kr];
        af[mt][1] = Asm[cur][rb + 8][kr];
        af[mt][2] = Asm[cur][rb    ][kr + 4];
        af[mt][3] = Asm[cur][rb + 8][kr + 4];
      }
      #pragma unroll
      for (int nt = 0; nt < 8; nt++){
        int nbc = warpN * 64 + nt * 8 + (lane >> 2);
        bf[nt][0] = Bsm[cur][nbc][kr];
        bf[nt][1] = Bsm[cur][nbc][kr + 4];
      }
      #pragma unroll
      for (int mt = 0; mt < 2; mt++)
        #pragma unroll
        for (int nt = 0; nt < 8; nt++)
          mma_tf32(acc[mt][nt], af[mt], bf[nt]);
    }
    __syncthreads();
  }
  float* op = out + ((size_t)b * 256) * PIX + pix0;
  #pragma unroll
  for (int mt = 0; mt < 2; mt++){
    #pragma unroll
    for (int ii = 0; ii < 2; ii++){
      int o = m0 + warpM * 32 + mt * 16 + (lane >> 2) + ii * 8;
      float bi = bias[o];
      #pragma unroll
      for (int nt = 0; nt < 8; nt++){
        int col = warpN * 64 + nt * 8 + (lane & 3) * 2;
        float2 v = make_float2(acc[mt][nt][ii*2] + bi, acc[mt][nt][ii*2+1] + bi);
        *(float2*)&op[(size_t)o * PIX + col] = v;
      }
    }
  }
}

// ---------------- launch ----------------
extern "C" void kernel_launch(void* const* d_in, const int* in_sizes, int n_in,
                              void* d_out, int out_size){
  const float* x      = (const float*)d_in[0];
  const float* w_qkv  = (const float*)d_in[1];
  const float* gtok   = (const float*)d_in[2];
  const float* gamma  = (const float*)d_in[3];
  const float* beta   = (const float*)d_in[4];
  const float* w_qk   = (const float*)d_in[5];
  const float* b_qk   = (const float*)d_in[6];
  const float* w_out  = (const float*)d_in[7];
  const float* b_out  = (const float*)d_in[8];
  float* out = (float*)d_out;

  float* d_gx; cudaGetSymbolAddress((void**)&d_gx, g_x);
  float* d_gw; cudaGetSymbolAddress((void**)&d_gw, g_wqkv);
  float* d_go; cudaGetSymbolAddress((void**)&d_go, g_wo);

  const int att_smem = 384 * 41 * 4;   // 63 KB dynamic
  cudaFuncSetAttribute(k_attn1, cudaFuncAttributeMaxDynamicSharedMemorySize, att_smem);

  k_zero <<<128, 256>>>();
  k_round<<<36864, 256>>>(d_gx, x, 9437184);
  k_round<<<192,   256>>>(d_gw, w_qkv, 49152);
  k_round<<<64,    256>>>(d_go, w_out, 16384);
  k_tok  <<<3, 256>>>(w_qkv, gtok);
  k_qkv  <<<dim3(1152, 6), 256>>>();
  k_attn1<<<8192, 256, att_smem>>>(gamma, beta);
  k_qk   <<<dim3(8, 4, 16), 256>>>(w_qk, b_qk);
  k_dots <<<dim3(8, 8, 128), 256>>>();
  k_agg  <<<dim3(3, 8, 128), 256>>>();
  k_out  <<<dim3(1152, 2), 256>>>(b_out, out);
}